// round 13
// baseline (speedup 1.0000x reference)
#include <cuda_runtime.h>
#include <math.h>
#include <stdint.h>

#define BB   4
#define CC   2048
#define DD   512
#define NHH  8
#define MTOT (BB * CC)      // 8192
#define HD   (NHH * DD)     // 4096

// ---------------- scratch (device globals: no allocation allowed) ----------------
__device__ float g_Q[(size_t)NHH * MTOT * DD];   // [h][m][d]
__device__ float g_K[(size_t)NHH * MTOT * DD];
__device__ float g_V[(size_t)NHH * MTOT * DD];
__device__ float g_S[(size_t)NHH * BB * CC * CC];   // [hb][q][k]
__device__ float g_O[(size_t)MTOT * HD];            // [b*C+c][h*D+d]
__device__ float g_ctab[CC * (DD / 2)];
__device__ float g_stab[CC * (DD / 2)];

// ---------------- RoPE cos/sin table ----------------
__global__ void rope_table_kernel() {
    int idx = blockIdx.x * blockDim.x + threadIdx.x;
    if (idx >= CC * (DD / 2)) return;
    int c = idx / (DD / 2);
    int i = idx - c * (DD / 2);
    double theta = exp((-2.0 * (double)i / (double)DD) * log(10000.0));
    double ang = fmod((double)c * theta, 6.283185307179586476925287);
    float af = (float)ang;
    g_ctab[idx] = cosf(af);
    g_stab[idx] = sinf(af);
}

// ---------------- TF32 helpers ----------------
__device__ __forceinline__ float to_tf32(float x) {
    uint32_t u;
    asm("cvt.rna.tf32.f32 %0, %1;" : "=r"(u) : "f"(x));
    return __uint_as_float(u);
}
__device__ __forceinline__ float4 to_tf32_4(float4 v) {
    return make_float4(to_tf32(v.x), to_tf32(v.y), to_tf32(v.z), to_tf32(v.w));
}

__device__ __forceinline__ void mma8(float* d, const float* a, const float* b) {
    asm volatile(
        "mma.sync.aligned.m16n8k8.row.col.f32.tf32.tf32.f32 "
        "{%0,%1,%2,%3}, {%4,%5,%6,%7}, {%8,%9}, {%0,%1,%2,%3};"
        : "+f"(d[0]), "+f"(d[1]), "+f"(d[2]), "+f"(d[3])
        : "r"(__float_as_uint(a[0])), "r"(__float_as_uint(a[1])),
          "r"(__float_as_uint(a[2])), "r"(__float_as_uint(a[3])),
          "r"(__float_as_uint(b[0])), "r"(__float_as_uint(b[1])));
}

// SMEM float offsets (dynamic smem)
//  As: [2][128][20]  at 0        (5120 floats)
//  Bs(bk): [2][16][264] at 5120  (8448 floats)  -> 13568 floats = 54272 B
//  Bs(bt): [2][256][20] at 5120  (10240 floats) -> 15360 floats = 61440 B
#define ASZ      (2 * 128 * 20)
#define SMEM_BK  (size_t)((ASZ + 2 * 16 * 264) * 4)
#define SMEM_BT  (size_t)((ASZ + 2 * 256 * 20) * 4)

// =====================================================================
// GEMM core, B k-major in global (B[k][n], n contiguous).
// Block tile 128(m) x 256(n), 256 threads, 8 warps = 2(m) x 4(n),
// warp tile 64x64. k-chunk 16, double-buffered, one sync per chunk.
// =====================================================================
__device__ __forceinline__ void gemm_bk256(
    const float* __restrict__ Ag, int lda,
    const float* __restrict__ Bg, int ldb,
    int ktiles, float (&acc)[4][8][4])
{
    extern __shared__ float sm[];
    float (*As)[128][20] = (float(*)[128][20])sm;
    float (*Bs)[16][264] = (float(*)[16][264])(sm + ASZ);

    const int tid  = threadIdx.x;
    const int lane = tid & 31, wid = tid >> 5;
    const int g = lane >> 2, t4 = lane & 3;
    const int wm = (wid >> 2) * 64, wn = (wid & 3) * 64;

    const int ar = tid >> 2, ac4 = (tid & 3) * 4;    // A loader
    float4 a0v, a1v, bv[4];
    a0v = *(const float4*)(Ag + (size_t)ar * lda + ac4);
    a1v = *(const float4*)(Ag + (size_t)(ar + 64) * lda + ac4);
#pragma unroll
    for (int i = 0; i < 4; ++i) {
        int s = tid + i * 256;
        bv[i] = *(const float4*)(Bg + (size_t)(s >> 6) * ldb + (s & 63) * 4);
    }

    for (int kt = 0; kt < ktiles; ++kt) {
        const int buf = kt & 1;
        *(float4*)&As[buf][ar][ac4]      = to_tf32_4(a0v);
        *(float4*)&As[buf][ar + 64][ac4] = to_tf32_4(a1v);
#pragma unroll
        for (int i = 0; i < 4; ++i) {
            int s = tid + i * 256;
            *(float4*)&Bs[buf][s >> 6][(s & 63) * 4] = to_tf32_4(bv[i]);
        }
        __syncthreads();
        if (kt + 1 < ktiles) {
            const float* Ap = Ag + (kt + 1) * 16;
            a0v = *(const float4*)(Ap + (size_t)ar * lda + ac4);
            a1v = *(const float4*)(Ap + (size_t)(ar + 64) * lda + ac4);
            const float* Bp = Bg + (size_t)(kt + 1) * 16 * ldb;
#pragma unroll
            for (int i = 0; i < 4; ++i) {
                int s = tid + i * 256;
                bv[i] = *(const float4*)(Bp + (size_t)(s >> 6) * ldb + (s & 63) * 4);
            }
        }
#pragma unroll
        for (int k0 = 0; k0 < 16; k0 += 8) {
            float a[4][4], b[8][2];
#pragma unroll
            for (int mi = 0; mi < 4; ++mi) {
                const int r = wm + mi * 16 + g;
                a[mi][0] = As[buf][r][k0 + t4];
                a[mi][1] = As[buf][r + 8][k0 + t4];
                a[mi][2] = As[buf][r][k0 + t4 + 4];
                a[mi][3] = As[buf][r + 8][k0 + t4 + 4];
            }
#pragma unroll
            for (int ni = 0; ni < 8; ++ni) {
                const int cn = wn + ni * 8 + g;
                b[ni][0] = Bs[buf][k0 + t4][cn];
                b[ni][1] = Bs[buf][k0 + t4 + 4][cn];
            }
#pragma unroll
            for (int mi = 0; mi < 4; ++mi)
#pragma unroll
                for (int ni = 0; ni < 8; ++ni)
                    mma8(acc[mi][ni], a[mi], b[ni]);
        }
    }
}

// =====================================================================
// GEMM core, B row-major k-contiguous (B[n][k]) -> C = A B^T. Same tiling.
// =====================================================================
__device__ __forceinline__ void gemm_bt256(
    const float* __restrict__ Ag, int lda,
    const float* __restrict__ Bg, int ldb,
    int ktiles, float (&acc)[4][8][4])
{
    extern __shared__ float sm[];
    float (*As)[128][20] = (float(*)[128][20])sm;
    float (*Bs)[256][20] = (float(*)[256][20])(sm + ASZ);

    const int tid  = threadIdx.x;
    const int lane = tid & 31, wid = tid >> 5;
    const int g = lane >> 2, t4 = lane & 3;
    const int wm = (wid >> 2) * 64, wn = (wid & 3) * 64;

    const int ar = tid >> 2, ac4 = (tid & 3) * 4;
    float4 a0v, a1v, bv[4];
    a0v = *(const float4*)(Ag + (size_t)ar * lda + ac4);
    a1v = *(const float4*)(Ag + (size_t)(ar + 64) * lda + ac4);
#pragma unroll
    for (int i = 0; i < 4; ++i) {
        int s = tid + i * 256;                     // row = s>>2 (0..255), col4 = (s&3)*4
        bv[i] = *(const float4*)(Bg + (size_t)(s >> 2) * ldb + (s & 3) * 4);
    }

    for (int kt = 0; kt < ktiles; ++kt) {
        const int buf = kt & 1;
        *(float4*)&As[buf][ar][ac4]      = to_tf32_4(a0v);
        *(float4*)&As[buf][ar + 64][ac4] = to_tf32_4(a1v);
#pragma unroll
        for (int i = 0; i < 4; ++i) {
            int s = tid + i * 256;
            *(float4*)&Bs[buf][s >> 2][(s & 3) * 4] = to_tf32_4(bv[i]);
        }
        __syncthreads();
        if (kt + 1 < ktiles) {
            const float* Ap = Ag + (kt + 1) * 16;
            a0v = *(const float4*)(Ap + (size_t)ar * lda + ac4);
            a1v = *(const float4*)(Ap + (size_t)(ar + 64) * lda + ac4);
            const float* Bp = Bg + (kt + 1) * 16;
#pragma unroll
            for (int i = 0; i < 4; ++i) {
                int s = tid + i * 256;
                bv[i] = *(const float4*)(Bp + (size_t)(s >> 2) * ldb + (s & 3) * 4);
            }
        }
#pragma unroll
        for (int k0 = 0; k0 < 16; k0 += 8) {
            float a[4][4], b[8][2];
#pragma unroll
            for (int mi = 0; mi < 4; ++mi) {
                const int r = wm + mi * 16 + g;
                a[mi][0] = As[buf][r][k0 + t4];
                a[mi][1] = As[buf][r + 8][k0 + t4];
                a[mi][2] = As[buf][r][k0 + t4 + 4];
                a[mi][3] = As[buf][r + 8][k0 + t4 + 4];
            }
#pragma unroll
            for (int ni = 0; ni < 8; ++ni) {
                const int cn = wn + ni * 8 + g;
                b[ni][0] = Bs[buf][cn][k0 + t4];
                b[ni][1] = Bs[buf][cn][k0 + t4 + 4];
            }
#pragma unroll
            for (int mi = 0; mi < 4; ++mi)
#pragma unroll
                for (int ni = 0; ni < 8; ++ni)
                    mma8(acc[mi][ni], a[mi], b[ni]);
        }
    }
}

#define ACC_INIT(acc)                                   \
    float acc[4][8][4];                                 \
    _Pragma("unroll")                                   \
    for (int _i = 0; _i < 4; ++_i)                      \
        _Pragma("unroll")                               \
        for (int _j = 0; _j < 8; ++_j)                  \
            _Pragma("unroll")                           \
            for (int _r = 0; _r < 4; ++_r) acc[_i][_j][_r] = 0.f;

// ---------------- Kernel 1: QKV projection + bias + RoPE ----------------
// grid (2 n, 64 m, 24 z); z = h*3 + t
__global__ __launch_bounds__(256, 1)
void qkv_mma(const float* __restrict__ x,
             const float* __restrict__ wq, const float* __restrict__ bq,
             const float* __restrict__ wk, const float* __restrict__ bk,
             const float* __restrict__ wv, const float* __restrict__ bv) {
    const int z = blockIdx.z;
    const int h = z / 3, t = z - 3 * h;
    const float* W; const float* bias; float* Out;
    if (t == 0)      { W = wq; bias = bq; Out = g_Q; }
    else if (t == 1) { W = wk; bias = bk; Out = g_K; }
    else             { W = wv; bias = bv; Out = g_V; }
    W    += (size_t)h * DD * DD;
    bias += h * DD;
    Out  += (size_t)h * MTOT * DD;

    const int m0 = blockIdx.y * 128, n0 = blockIdx.x * 256;
    ACC_INIT(acc);
    gemm_bk256(x + (size_t)m0 * DD, DD, W + n0, DD, DD / 16, acc);

    const int lane = threadIdx.x & 31, wid = threadIdx.x >> 5;
    const int g = lane >> 2, t4 = lane & 3;
    const int wm = (wid >> 2) * 64, wn = (wid & 3) * 64;

#pragma unroll
    for (int mi = 0; mi < 4; ++mi) {
        const int mlo = m0 + wm + mi * 16 + g;
        const int mhi = mlo + 8;
#pragma unroll
        for (int ni = 0; ni < 8; ++ni) {
            const int n = n0 + wn + ni * 8 + 2 * t4;
            float2 bb = *(const float2*)(bias + n);
            float o0 = acc[mi][ni][0] + bb.x;
            float o1 = acc[mi][ni][1] + bb.y;
            float o2 = acc[mi][ni][2] + bb.x;
            float o3 = acc[mi][ni][3] + bb.y;
            if (t < 2) {
                const int p = n >> 1;
                const int clo = mlo & (CC - 1), chi = mhi & (CC - 1);
                float cs = g_ctab[clo * 256 + p], sn = g_stab[clo * 256 + p];
                float e = o0, od = o1;
                o0 = e * cs - od * sn; o1 = e * sn + od * cs;
                cs = g_ctab[chi * 256 + p]; sn = g_stab[chi * 256 + p];
                e = o2; od = o3;
                o2 = e * cs - od * sn; o3 = e * sn + od * cs;
            }
            *(float2*)(Out + (size_t)mlo * DD + n) = make_float2(o0, o1);
            *(float2*)(Out + (size_t)mhi * DD + n) = make_float2(o2, o3);
        }
    }
}

// ---------------- Kernel 2: S = Q K^T * scale (causal 128x256 tiles) ----------------
// grid (8 kt, 16 qt, 32 hb); keep iff 2*kt <= qt
__global__ __launch_bounds__(256, 1)
void scores_mma() {
    const int hb = blockIdx.z, qt = blockIdx.y, kt = blockIdx.x;
    if (2 * kt > qt) return;

    const float* Qp = g_Q + (size_t)hb * CC * DD;
    const float* Kp = g_K + (size_t)hb * CC * DD;
    float* Sp = g_S + (size_t)hb * CC * CC;
    const int m0 = qt * 128, n0 = kt * 256;

    ACC_INIT(acc);
    gemm_bt256(Qp + (size_t)m0 * DD, DD, Kp + (size_t)n0 * DD, DD, DD / 16, acc);

    const int lane = threadIdx.x & 31, wid = threadIdx.x >> 5;
    const int g = lane >> 2, t4 = lane & 3;
    const int wm = (wid >> 2) * 64, wn = (wid & 3) * 64;
    const float scale = 0.04419417382415922f;  // 1/sqrt(512)

#pragma unroll
    for (int mi = 0; mi < 4; ++mi) {
        const int qlo = m0 + wm + mi * 16 + g;
        const int qhi = qlo + 8;
#pragma unroll
        for (int ni = 0; ni < 8; ++ni) {
            const int n = n0 + wn + ni * 8 + 2 * t4;
            float o0 = (n     <= qlo) ? acc[mi][ni][0] * scale : -1e30f;
            float o1 = (n + 1 <= qlo) ? acc[mi][ni][1] * scale : -1e30f;
            float o2 = (n     <= qhi) ? acc[mi][ni][2] * scale : -1e30f;
            float o3 = (n + 1 <= qhi) ? acc[mi][ni][3] * scale : -1e30f;
            *(float2*)(Sp + (size_t)qlo * CC + n) = make_float2(o0, o1);
            *(float2*)(Sp + (size_t)qhi * CC + n) = make_float2(o2, o3);
        }
    }
}

// ---------------- Kernel 3: row softmax (256-granular causal length) ----------------
__global__ __launch_bounds__(256)
void softmax_kernel() {
    const int q = blockIdx.x, hb = blockIdx.y;
    float* row = g_S + (size_t)hb * CC * CC + (size_t)q * CC;
    const int L4 = (((q >> 8) + 1) << 8) >> 2;   // float4 count
    const int tid = threadIdx.x;

    float4 v[2];
    float mx = -3.4e38f;
#pragma unroll
    for (int u = 0; u < 2; ++u) {
        int i4 = tid + u * 256;
        v[u] = (i4 < L4) ? ((const float4*)row)[i4]
                         : make_float4(-3.4e38f, -3.4e38f, -3.4e38f, -3.4e38f);
        mx = fmaxf(mx, fmaxf(fmaxf(v[u].x, v[u].y), fmaxf(v[u].z, v[u].w)));
    }
    __shared__ float red[256];
    red[tid] = mx; __syncthreads();
    for (int o = 128; o > 0; o >>= 1) {
        if (tid < o) red[tid] = fmaxf(red[tid], red[tid + o]);
        __syncthreads();
    }
    mx = red[0];
    __syncthreads();

    float s = 0.f;
#pragma unroll
    for (int u = 0; u < 2; ++u) {
        v[u].x = expf(v[u].x - mx); v[u].y = expf(v[u].y - mx);
        v[u].z = expf(v[u].z - mx); v[u].w = expf(v[u].w - mx);
        s += v[u].x + v[u].y + v[u].z + v[u].w;
    }
    red[tid] = s; __syncthreads();
    for (int o = 128; o > 0; o >>= 1) {
        if (tid < o) red[tid] += red[tid + o];
        __syncthreads();
    }
    const float inv = 1.0f / red[0];
#pragma unroll
    for (int u = 0; u < 2; ++u) {
        int i4 = tid + u * 256;
        if (i4 < L4)
            ((float4*)row)[i4] = make_float4(v[u].x * inv, v[u].y * inv,
                                             v[u].z * inv, v[u].w * inv);
    }
}

// ---------------- Kernel 4: O = P @ V (K extent 256-granular per q-tile) ----------------
// grid (2 nt, 16 qt, 32 hb)
__global__ __launch_bounds__(256, 1)
void pv_mma() {
    const int hb = blockIdx.z, qt = blockIdx.y, nt = blockIdx.x;
    const float* P  = g_S + (size_t)hb * CC * CC;
    const float* Vp = g_V + (size_t)hb * CC * DD;

    const int m0 = qt * 128, n0 = nt * 256;
    const int ktiles = ((qt >> 1) + 1) * 16;     // 256-col chunks of defined S

    ACC_INIT(acc);
    gemm_bk256(P + (size_t)m0 * CC, CC, Vp + n0, DD, ktiles, acc);

    const int lane = threadIdx.x & 31, wid = threadIdx.x >> 5;
    const int g = lane >> 2, t4 = lane & 3;
    const int wm = (wid >> 2) * 64, wn = (wid & 3) * 64;
    const int h = hb >> 2, b = hb & 3;

#pragma unroll
    for (int mi = 0; mi < 4; ++mi) {
        const int mlo = m0 + wm + mi * 16 + g;
        const int mhi = mlo + 8;
#pragma unroll
        for (int ni = 0; ni < 8; ++ni) {
            const int n = n0 + wn + ni * 8 + 2 * t4;
            float* plo = g_O + (size_t)(b * CC + mlo) * HD + (size_t)h * DD + n;
            float* phi = g_O + (size_t)(b * CC + mhi) * HD + (size_t)h * DD + n;
            *(float2*)plo = make_float2(acc[mi][ni][0], acc[mi][ni][1]);
            *(float2*)phi = make_float2(acc[mi][ni][2], acc[mi][ni][3]);
        }
    }
}

// ---------------- Kernel 5: final projection + bias ----------------
// grid (2 n, 64 m)
__global__ __launch_bounds__(256, 1)
void outproj_mma(const float* __restrict__ wo, const float* __restrict__ bo,
                 float* __restrict__ out) {
    const int m0 = blockIdx.y * 128, n0 = blockIdx.x * 256;

    ACC_INIT(acc);
    gemm_bk256(g_O + (size_t)m0 * HD, HD, wo + n0, DD, HD / 16, acc);

    const int lane = threadIdx.x & 31, wid = threadIdx.x >> 5;
    const int g = lane >> 2, t4 = lane & 3;
    const int wm = (wid >> 2) * 64, wn = (wid & 3) * 64;

#pragma unroll
    for (int mi = 0; mi < 4; ++mi) {
        const int mlo = m0 + wm + mi * 16 + g;
        const int mhi = mlo + 8;
#pragma unroll
        for (int ni = 0; ni < 8; ++ni) {
            const int n = n0 + wn + ni * 8 + 2 * t4;
            float2 bb = *(const float2*)(bo + n);
            *(float2*)(out + (size_t)mlo * DD + n) =
                make_float2(acc[mi][ni][0] + bb.x, acc[mi][ni][1] + bb.y);
            *(float2*)(out + (size_t)mhi * DD + n) =
                make_float2(acc[mi][ni][2] + bb.x, acc[mi][ni][3] + bb.y);
        }
    }
}

// ---------------- launch ----------------
extern "C" void kernel_launch(void* const* d_in, const int* in_sizes, int n_in,
                              void* d_out, int out_size) {
    (void)in_sizes; (void)n_in; (void)out_size;
    const float* x  = (const float*)d_in[0];
    const float* wq = (const float*)d_in[1];
    const float* bq = (const float*)d_in[2];
    const float* wk = (const float*)d_in[3];
    const float* bk = (const float*)d_in[4];
    const float* wv = (const float*)d_in[5];
    const float* bv = (const float*)d_in[6];
    const float* wo = (const float*)d_in[7];
    const float* bo = (const float*)d_in[8];
    float* out = (float*)d_out;

    cudaFuncSetAttribute(qkv_mma,     cudaFuncAttributeMaxDynamicSharedMemorySize, (int)SMEM_BK);
    cudaFuncSetAttribute(scores_mma,  cudaFuncAttributeMaxDynamicSharedMemorySize, (int)SMEM_BT);
    cudaFuncSetAttribute(pv_mma,      cudaFuncAttributeMaxDynamicSharedMemorySize, (int)SMEM_BK);
    cudaFuncSetAttribute(outproj_mma, cudaFuncAttributeMaxDynamicSharedMemorySize, (int)SMEM_BK);

    rope_table_kernel<<<(CC * (DD / 2) + 255) / 256, 256>>>();
    qkv_mma    <<<dim3(2, 64, 24), 256, SMEM_BK>>>(x, wq, bq, wk, bk, wv, bv);
    scores_mma <<<dim3(8, 16, 32), 256, SMEM_BT>>>();
    softmax_kernel<<<dim3(CC, 32), 256>>>();
    pv_mma     <<<dim3(2, 16, 32), 256, SMEM_BK>>>();
    outproj_mma<<<dim3(2, 64, 1),  256, SMEM_BK>>>(wo, bo, out);
}

// round 14
// speedup vs baseline: 1.5894x; 1.5894x over previous
#include <cuda_runtime.h>
#include <cuda_fp16.h>
#include <math.h>
#include <stdint.h>

#define BB   4
#define CC   2048
#define DD   512
#define NHH  8
#define MTOT (BB * CC)      // 8192
#define HD   (NHH * DD)     // 4096

// ---------------- scratch (device globals: no allocation allowed) ----------------
__device__ __half g_Xh [(size_t)MTOT * DD];           // x in half
__device__ __half g_Qh [(size_t)NHH * MTOT * DD];     // [h][m][d]
__device__ __half g_Kh [(size_t)NHH * MTOT * DD];
__device__ __half g_VTh[(size_t)NHH * BB * DD * CC];  // [hb][d][c]
__device__ __half g_Ph [(size_t)NHH * BB * CC * CC];  // [hb][q][k]  probs half
__device__ __half g_Oh [(size_t)MTOT * HD];           // [b*C+c][h*D+d]
__device__ __half g_WqTh[(size_t)NHH * DD * DD];      // [h][n][k]
__device__ __half g_WkTh[(size_t)NHH * DD * DD];
__device__ __half g_WvTh[(size_t)NHH * DD * DD];
__device__ __half g_WoTh[(size_t)DD * HD];            // [n][k]
__device__ float  g_S  [(size_t)NHH * BB * CC * CC];  // scores fp32
__device__ float  g_ctab[CC * (DD / 2)];
__device__ float  g_stab[CC * (DD / 2)];

// ---------------- RoPE cos/sin table ----------------
__global__ void rope_table_kernel() {
    int idx = blockIdx.x * blockDim.x + threadIdx.x;
    if (idx >= CC * (DD / 2)) return;
    int c = idx / (DD / 2);
    int i = idx - c * (DD / 2);
    double theta = exp((-2.0 * (double)i / (double)DD) * log(10000.0));
    double ang = fmod((double)c * theta, 6.283185307179586476925287);
    float af = (float)ang;
    g_ctab[idx] = cosf(af);
    g_stab[idx] = sinf(af);
}

// ---------------- x -> half ----------------
__global__ void conv_x_kernel(const float* __restrict__ x) {
    int i = blockIdx.x * blockDim.x + threadIdx.x;
    if (i < MTOT * DD) g_Xh[i] = __float2half_rn(x[i]);
}

// ---------------- fp32 [R][C] -> half [C][R] (batched over z) ----------------
__global__ void transpose_h_kernel(const float* __restrict__ src, __half* __restrict__ dst,
                                   int R, int C) {
    __shared__ float tsm[32][33];
    src += (size_t)blockIdx.z * R * C;
    dst += (size_t)blockIdx.z * R * C;
    int r0 = blockIdx.y * 32, c0 = blockIdx.x * 32;
    int x = threadIdx.x, y = threadIdx.y;
#pragma unroll
    for (int i = 0; i < 32; i += 8)
        tsm[y + i][x] = src[(size_t)(r0 + y + i) * C + c0 + x];
    __syncthreads();
#pragma unroll
    for (int i = 0; i < 32; i += 8)
        dst[(size_t)(c0 + y + i) * R + r0 + x] = __float2half_rn(tsm[x][y + i]);
}

// ---------------- fp16 MMA ----------------
__device__ __forceinline__ void mma16(float* d, const uint32_t* a, const uint32_t* b) {
    asm volatile(
        "mma.sync.aligned.m16n8k16.row.col.f32.f16.f16.f32 "
        "{%0,%1,%2,%3}, {%4,%5,%6,%7}, {%8,%9}, {%0,%1,%2,%3};"
        : "+f"(d[0]), "+f"(d[1]), "+f"(d[2]), "+f"(d[3])
        : "r"(a[0]), "r"(a[1]), "r"(a[2]), "r"(a[3]),
          "r"(b[0]), "r"(b[1]));
}

// smem: As [2][128][40] halfs, Bs [2][256][40] halfs  (40 = 32 + 8 pad -> 80B rows)
#define AHW    40
#define ASZ_H  (2 * 128 * AHW)
#define BSZ_H  (2 * 256 * AHW)
#define SMEM_H (size_t)((ASZ_H + BSZ_H) * 2)   // 61440 bytes

// =====================================================================
// fp16 GEMM core: C[128 x 256] = A[128 x K] * B[256 x K]^T
// A rows k-contiguous (lda halfs), B rows k-contiguous (ldb halfs).
// 256 threads, 8 warps = 2(m) x 4(n), warp tile 64x64, k-chunk 32,
// double-buffered smem, one __syncthreads per chunk.
// =====================================================================
__device__ __forceinline__ void gemm_bt_h(
    const __half* __restrict__ Ag, int lda,
    const __half* __restrict__ Bg, int ldb,
    int nchunks, float (&acc)[4][8][4])
{
    extern __shared__ __half smh[];
    __half (*As)[128][AHW] = (__half(*)[128][AHW])smh;
    __half (*Bs)[256][AHW] = (__half(*)[256][AHW])(smh + ASZ_H);

    const int tid  = threadIdx.x;
    const int lane = tid & 31, wid = tid >> 5;
    const int g = lane >> 2, t4 = lane & 3;
    const int wm = (wid >> 2) * 64, wn = (wid & 3) * 64;

    uint4 av[2], bv[4];
#pragma unroll
    for (int i = 0; i < 2; ++i) {
        int s = tid + i * 256;
        av[i] = *(const uint4*)(Ag + (size_t)(s >> 2) * lda + (s & 3) * 8);
    }
#pragma unroll
    for (int i = 0; i < 4; ++i) {
        int s = tid + i * 256;
        bv[i] = *(const uint4*)(Bg + (size_t)(s >> 2) * ldb + (s & 3) * 8);
    }

    for (int kt = 0; kt < nchunks; ++kt) {
        const int buf = kt & 1;
#pragma unroll
        for (int i = 0; i < 2; ++i) {
            int s = tid + i * 256;
            *(uint4*)&As[buf][s >> 2][(s & 3) * 8] = av[i];
        }
#pragma unroll
        for (int i = 0; i < 4; ++i) {
            int s = tid + i * 256;
            *(uint4*)&Bs[buf][s >> 2][(s & 3) * 8] = bv[i];
        }
        __syncthreads();
        if (kt + 1 < nchunks) {
            const __half* Ap = Ag + (kt + 1) * 32;
            const __half* Bp = Bg + (kt + 1) * 32;
#pragma unroll
            for (int i = 0; i < 2; ++i) {
                int s = tid + i * 256;
                av[i] = *(const uint4*)(Ap + (size_t)(s >> 2) * lda + (s & 3) * 8);
            }
#pragma unroll
            for (int i = 0; i < 4; ++i) {
                int s = tid + i * 256;
                bv[i] = *(const uint4*)(Bp + (size_t)(s >> 2) * ldb + (s & 3) * 8);
            }
        }
#pragma unroll
        for (int k0 = 0; k0 < 32; k0 += 16) {
            uint32_t a[4][4], b[8][2];
#pragma unroll
            for (int mi = 0; mi < 4; ++mi) {
                const int r = wm + mi * 16 + g;
                a[mi][0] = *(const uint32_t*)&As[buf][r][k0 + 2 * t4];
                a[mi][1] = *(const uint32_t*)&As[buf][r + 8][k0 + 2 * t4];
                a[mi][2] = *(const uint32_t*)&As[buf][r][k0 + 2 * t4 + 8];
                a[mi][3] = *(const uint32_t*)&As[buf][r + 8][k0 + 2 * t4 + 8];
            }
#pragma unroll
            for (int ni = 0; ni < 8; ++ni) {
                const int cn = wn + ni * 8 + g;
                b[ni][0] = *(const uint32_t*)&Bs[buf][cn][k0 + 2 * t4];
                b[ni][1] = *(const uint32_t*)&Bs[buf][cn][k0 + 2 * t4 + 8];
            }
#pragma unroll
            for (int mi = 0; mi < 4; ++mi)
#pragma unroll
                for (int ni = 0; ni < 8; ++ni)
                    mma16(acc[mi][ni], a[mi], b[ni]);
        }
    }
}

#define ACC_INIT(acc)                                   \
    float acc[4][8][4];                                 \
    _Pragma("unroll")                                   \
    for (int _i = 0; _i < 4; ++_i)                      \
        _Pragma("unroll")                               \
        for (int _j = 0; _j < 8; ++_j)                  \
            _Pragma("unroll")                           \
            for (int _r = 0; _r < 4; ++_r) acc[_i][_j][_r] = 0.f;

// ---------------- Kernel 1: QKV projection + bias + RoPE ----------------
// grid (2 n, 64 m, 24 z); z = h*3 + t
__global__ __launch_bounds__(256, 1)
void qkv_f16(const float* __restrict__ bq, const float* __restrict__ bk,
             const float* __restrict__ bvv) {
    const int z = blockIdx.z;
    const int h = z / 3, t = z - 3 * h;
    const __half* WT = (t == 0 ? g_WqTh : (t == 1 ? g_WkTh : g_WvTh)) + (size_t)h * DD * DD;
    const float* bias = (t == 0 ? bq : (t == 1 ? bk : bvv)) + h * DD;

    const int m0 = blockIdx.y * 128, n0 = blockIdx.x * 256;
    ACC_INIT(acc);
    gemm_bt_h(g_Xh + (size_t)m0 * DD, DD, WT + (size_t)n0 * DD, DD, DD / 32, acc);

    const int lane = threadIdx.x & 31, wid = threadIdx.x >> 5;
    const int g = lane >> 2, t4 = lane & 3;
    const int wm = (wid >> 2) * 64, wn = (wid & 3) * 64;

#pragma unroll
    for (int mi = 0; mi < 4; ++mi) {
        const int mlo = m0 + wm + mi * 16 + g;
        const int mhi = mlo + 8;
#pragma unroll
        for (int ni = 0; ni < 8; ++ni) {
            const int n = n0 + wn + ni * 8 + 2 * t4;
            float2 bb = *(const float2*)(bias + n);
            float o0 = acc[mi][ni][0] + bb.x;
            float o1 = acc[mi][ni][1] + bb.y;
            float o2 = acc[mi][ni][2] + bb.x;
            float o3 = acc[mi][ni][3] + bb.y;
            if (t < 2) {
                __half* Out = (t == 0 ? g_Qh : g_Kh) + (size_t)h * MTOT * DD;
                const int p = n >> 1;
                const int clo = mlo & (CC - 1), chi = mhi & (CC - 1);
                float cs = g_ctab[clo * 256 + p], sn = g_stab[clo * 256 + p];
                float e = o0, od = o1;
                o0 = e * cs - od * sn; o1 = e * sn + od * cs;
                cs = g_ctab[chi * 256 + p]; sn = g_stab[chi * 256 + p];
                e = o2; od = o3;
                o2 = e * cs - od * sn; o3 = e * sn + od * cs;
                *(__half2*)(Out + (size_t)mlo * DD + n) = __floats2half2_rn(o0, o1);
                *(__half2*)(Out + (size_t)mhi * DD + n) = __floats2half2_rn(o2, o3);
            } else {
                const int blo = mlo >> 11, clo = mlo & (CC - 1);
                const int bhi = mhi >> 11, chi = mhi & (CC - 1);
                __half* vlo = g_VTh + (size_t)(h * BB + blo) * DD * CC;
                __half* vhi = g_VTh + (size_t)(h * BB + bhi) * DD * CC;
                vlo[(size_t)n * CC + clo]       = __float2half_rn(o0);
                vlo[(size_t)(n + 1) * CC + clo] = __float2half_rn(o1);
                vhi[(size_t)n * CC + chi]       = __float2half_rn(o2);
                vhi[(size_t)(n + 1) * CC + chi] = __float2half_rn(o3);
            }
        }
    }
}

// ---------------- Kernel 2: S = Q K^T * scale (causal 128x256 tiles, fp32 out) ----------------
// grid (8 kt, 16 qt, 32 hb); keep iff 2*kt <= qt
__global__ __launch_bounds__(256, 1)
void scores_f16() {
    const int hb = blockIdx.z, qt = blockIdx.y, kt = blockIdx.x;
    if (2 * kt > qt) return;

    const __half* Qp = g_Qh + (size_t)hb * CC * DD;
    const __half* Kp = g_Kh + (size_t)hb * CC * DD;
    float* Sp = g_S + (size_t)hb * CC * CC;
    const int m0 = qt * 128, n0 = kt * 256;

    ACC_INIT(acc);
    gemm_bt_h(Qp + (size_t)m0 * DD, DD, Kp + (size_t)n0 * DD, DD, DD / 32, acc);

    const int lane = threadIdx.x & 31, wid = threadIdx.x >> 5;
    const int g = lane >> 2, t4 = lane & 3;
    const int wm = (wid >> 2) * 64, wn = (wid & 3) * 64;
    const float scale = 0.04419417382415922f;  // 1/sqrt(512)

#pragma unroll
    for (int mi = 0; mi < 4; ++mi) {
        const int qlo = m0 + wm + mi * 16 + g;
        const int qhi = qlo + 8;
#pragma unroll
        for (int ni = 0; ni < 8; ++ni) {
            const int n = n0 + wn + ni * 8 + 2 * t4;
            float o0 = (n     <= qlo) ? acc[mi][ni][0] * scale : -1e30f;
            float o1 = (n + 1 <= qlo) ? acc[mi][ni][1] * scale : -1e30f;
            float o2 = (n     <= qhi) ? acc[mi][ni][2] * scale : -1e30f;
            float o3 = (n + 1 <= qhi) ? acc[mi][ni][3] * scale : -1e30f;
            *(float2*)(Sp + (size_t)qlo * CC + n) = make_float2(o0, o1);
            *(float2*)(Sp + (size_t)qhi * CC + n) = make_float2(o2, o3);
        }
    }
}

// ---------------- Kernel 3: softmax, fp32 in -> half probs out ----------------
__global__ __launch_bounds__(256)
void softmax_kernel() {
    const int q = blockIdx.x, hb = blockIdx.y;
    float* row  = g_S  + (size_t)hb * CC * CC + (size_t)q * CC;
    __half* prow = g_Ph + (size_t)hb * CC * CC + (size_t)q * CC;
    const int L4 = (((q >> 8) + 1) << 8) >> 2;
    const int tid = threadIdx.x;

    float4 v[2];
    float mx = -3.4e38f;
#pragma unroll
    for (int u = 0; u < 2; ++u) {
        int i4 = tid + u * 256;
        v[u] = (i4 < L4) ? ((const float4*)row)[i4]
                         : make_float4(-3.4e38f, -3.4e38f, -3.4e38f, -3.4e38f);
        mx = fmaxf(mx, fmaxf(fmaxf(v[u].x, v[u].y), fmaxf(v[u].z, v[u].w)));
    }
    __shared__ float red[256];
    red[tid] = mx; __syncthreads();
    for (int o = 128; o > 0; o >>= 1) {
        if (tid < o) red[tid] = fmaxf(red[tid], red[tid + o]);
        __syncthreads();
    }
    mx = red[0];
    __syncthreads();

    float s = 0.f;
#pragma unroll
    for (int u = 0; u < 2; ++u) {
        v[u].x = expf(v[u].x - mx); v[u].y = expf(v[u].y - mx);
        v[u].z = expf(v[u].z - mx); v[u].w = expf(v[u].w - mx);
        s += v[u].x + v[u].y + v[u].z + v[u].w;
    }
    red[tid] = s; __syncthreads();
    for (int o = 128; o > 0; o >>= 1) {
        if (tid < o) red[tid] += red[tid + o];
        __syncthreads();
    }
    const float inv = 1.0f / red[0];
#pragma unroll
    for (int u = 0; u < 2; ++u) {
        int i4 = tid + u * 256;
        if (i4 < L4) {
            __half2 h01 = __floats2half2_rn(v[u].x * inv, v[u].y * inv);
            __half2 h23 = __floats2half2_rn(v[u].z * inv, v[u].w * inv);
            ((__half2*)prow)[i4 * 2]     = h01;
            ((__half2*)prow)[i4 * 2 + 1] = h23;
        }
    }
}

// ---------------- Kernel 4: O = P @ V  (B = V^T half, K extent 256-granular) ----------------
// grid (2 nt, 16 qt, 32 hb)
__global__ __launch_bounds__(256, 1)
void pv_f16() {
    const int hb = blockIdx.z, qt = blockIdx.y, nt = blockIdx.x;
    const __half* P  = g_Ph  + (size_t)hb * CC * CC;
    const __half* VT = g_VTh + (size_t)hb * DD * CC;

    const int m0 = qt * 128, n0 = nt * 256;
    const int nchunks = ((qt >> 1) + 1) * 8;   // k-extent in 32-half chunks

    ACC_INIT(acc);
    gemm_bt_h(P + (size_t)m0 * CC, CC, VT + (size_t)n0 * CC, CC, nchunks, acc);

    const int lane = threadIdx.x & 31, wid = threadIdx.x >> 5;
    const int g = lane >> 2, t4 = lane & 3;
    const int wm = (wid >> 2) * 64, wn = (wid & 3) * 64;
    const int h = hb >> 2, b = hb & 3;

#pragma unroll
    for (int mi = 0; mi < 4; ++mi) {
        const int mlo = m0 + wm + mi * 16 + g;
        const int mhi = mlo + 8;
#pragma unroll
        for (int ni = 0; ni < 8; ++ni) {
            const int n = n0 + wn + ni * 8 + 2 * t4;
            __half* plo = g_Oh + (size_t)(b * CC + mlo) * HD + (size_t)h * DD + n;
            __half* phi = g_Oh + (size_t)(b * CC + mhi) * HD + (size_t)h * DD + n;
            *(__half2*)plo = __floats2half2_rn(acc[mi][ni][0], acc[mi][ni][1]);
            *(__half2*)phi = __floats2half2_rn(acc[mi][ni][2], acc[mi][ni][3]);
        }
    }
}

// ---------------- Kernel 5: final projection + bias (fp32 out) ----------------
// grid (2 n, 64 m)
__global__ __launch_bounds__(256, 1)
void outproj_f16(const float* __restrict__ bo, float* __restrict__ out) {
    const int m0 = blockIdx.y * 128, n0 = blockIdx.x * 256;

    ACC_INIT(acc);
    gemm_bt_h(g_Oh + (size_t)m0 * HD, HD, g_WoTh + (size_t)n0 * HD, HD, HD / 32, acc);

    const int lane = threadIdx.x & 31, wid = threadIdx.x >> 5;
    const int g = lane >> 2, t4 = lane & 3;
    const int wm = (wid >> 2) * 64, wn = (wid & 3) * 64;

#pragma unroll
    for (int mi = 0; mi < 4; ++mi) {
        const int mlo = m0 + wm + mi * 16 + g;
        const int mhi = mlo + 8;
#pragma unroll
        for (int ni = 0; ni < 8; ++ni) {
            const int n = n0 + wn + ni * 8 + 2 * t4;
            float2 bb = *(const float2*)(bo + n);
            *(float2*)(out + (size_t)mlo * DD + n) =
                make_float2(acc[mi][ni][0] + bb.x, acc[mi][ni][1] + bb.y);
            *(float2*)(out + (size_t)mhi * DD + n) =
                make_float2(acc[mi][ni][2] + bb.x, acc[mi][ni][3] + bb.y);
        }
    }
}

// ---------------- launch ----------------
extern "C" void kernel_launch(void* const* d_in, const int* in_sizes, int n_in,
                              void* d_out, int out_size) {
    (void)in_sizes; (void)n_in; (void)out_size;
    const float* x  = (const float*)d_in[0];
    const float* wq = (const float*)d_in[1];
    const float* bq = (const float*)d_in[2];
    const float* wk = (const float*)d_in[3];
    const float* bk = (const float*)d_in[4];
    const float* wv = (const float*)d_in[5];
    const float* bv = (const float*)d_in[6];
    const float* wo = (const float*)d_in[7];
    const float* bo = (const float*)d_in[8];
    float* out = (float*)d_out;

    cudaFuncSetAttribute(qkv_f16,     cudaFuncAttributeMaxDynamicSharedMemorySize, (int)SMEM_H);
    cudaFuncSetAttribute(scores_f16,  cudaFuncAttributeMaxDynamicSharedMemorySize, (int)SMEM_H);
    cudaFuncSetAttribute(pv_f16,      cudaFuncAttributeMaxDynamicSharedMemorySize, (int)SMEM_H);
    cudaFuncSetAttribute(outproj_f16, cudaFuncAttributeMaxDynamicSharedMemorySize, (int)SMEM_H);

    __half *pWqT, *pWkT, *pWvT, *pWoT;
    cudaGetSymbolAddress((void**)&pWqT, g_WqTh);
    cudaGetSymbolAddress((void**)&pWkT, g_WkTh);
    cudaGetSymbolAddress((void**)&pWvT, g_WvTh);
    cudaGetSymbolAddress((void**)&pWoT, g_WoTh);

    rope_table_kernel<<<(CC * (DD / 2) + 255) / 256, 256>>>();
    conv_x_kernel<<<(MTOT * DD) / 256, 256>>>(x);
    transpose_h_kernel<<<dim3(16, 16, 8),  dim3(32, 8)>>>(wq, pWqT, DD, DD);
    transpose_h_kernel<<<dim3(16, 16, 8),  dim3(32, 8)>>>(wk, pWkT, DD, DD);
    transpose_h_kernel<<<dim3(16, 16, 8),  dim3(32, 8)>>>(wv, pWvT, DD, DD);
    transpose_h_kernel<<<dim3(16, 128, 1), dim3(32, 8)>>>(wo, pWoT, HD, DD);

    qkv_f16    <<<dim3(2, 64, 24), 256, SMEM_H>>>(bq, bk, bv);
    scores_f16 <<<dim3(8, 16, 32), 256, SMEM_H>>>();
    softmax_kernel<<<dim3(CC, 32), 256>>>();
    pv_f16     <<<dim3(2, 16, 32), 256, SMEM_H>>>();
    outproj_f16<<<dim3(2, 64, 1),  256, SMEM_H>>>(bo, out);
}